// round 7
// baseline (speedup 1.0000x reference)
#include <cuda_runtime.h>

// metaLinear: y[t,o] = sum_{i,j} x1[t,i]*x2[t,j]*W[j*64+o, i] + sum_j x2[t,j]*b[j*64+o]
// Refactored as GEMM: Y(T x 64) = P(T x 16448) @ Wt(16448 x 64)
//   k = i*64 + j   (i < 256), P[t,k] = x1[t,i]*x2[t,j]
//   k = 16384 + j  (bias),    P[t,k] = x2[t,j]          (x1 == 1)
//   Wt[k][o] = W[(j*64+o)*256 + i] ; bias rows Wt[16384+j][o] = bvec[j*64+o]

#define IN1     256
#define IN2     64
#define OUTDIM  64
#define KTOT    (IN1 * IN2)      // 16384
#define NCHUNK  (IN1 + 1)        // 257 chunks of 64 k each (last = bias)
#define TB      64               // tokens per CTA
#define THREADS 256

// 4.21 MB device scratch for the transposed weight (+ bias rows)
__device__ float g_Wt[(KTOT + IN2) * OUTDIM];

// ---------------------------------------------------------------------------
// Prep 1: tiled transpose  W(4096 x 256) -> Wt flat index i*4096 + r  (r = j*64+o)
// ---------------------------------------------------------------------------
__global__ void prep_transpose(const float* __restrict__ W) {
    __shared__ float tile[32][33];
    const int ib = blockIdx.x * 32;   // i block (0..255)
    const int rb = blockIdx.y * 32;   // r block (0..4095)
    const int tx = threadIdx.x;       // 0..31
    const int ty = threadIdx.y;       // 0..7
#pragma unroll
    for (int yy = 0; yy < 32; yy += 8)
        tile[ty + yy][tx] = W[(size_t)(rb + ty + yy) * IN1 + (ib + tx)];
    __syncthreads();
#pragma unroll
    for (int yy = 0; yy < 32; yy += 8)
        g_Wt[(size_t)(ib + ty + yy) * (IN2 * OUTDIM) + (rb + tx)] = tile[tx][ty + yy];
}

// Prep 2: bias rows — Wt rows [16384..16447] are just bvec reshaped (contiguous)
__global__ void prep_bias(const float* __restrict__ bvec) {
    int m = blockIdx.x * 256 + threadIdx.x;      // 0..4095
    g_Wt[(size_t)KTOT * OUTDIM + m] = bvec[m];
}

// ---------------------------------------------------------------------------
// Main GEMM. 256 threads / CTA, 64 tokens / CTA.
// Thread micro-tile: 2 tokens x 8 outputs, accumulated as f32x2 pairs (FFMA2).
//   t_grp = tid>>3 (0..31) -> tokens tt0 = 2*t_grp
//   o_grp = tid&7  (0..7)  -> outputs oo0 = 8*o_grp
// ---------------------------------------------------------------------------
__global__ __launch_bounds__(THREADS) void metalinear_kernel(
    const float* __restrict__ x1,
    const float* __restrict__ x2,
    float* __restrict__ out)
{
    __shared__ __align__(16) float X2s[IN2][TB + 4];            // [j][t], padded rows
    __shared__ __align__(16) float4 Wbuf4[IN2 * OUTDIM / 4];    // 16 KB, view [j][o]

    const int tid   = threadIdx.x;
    const int t_grp = tid >> 3;      // 0..31
    const int o_grp = tid & 7;       // 0..7
    const int tok0  = blockIdx.x * TB;
    const int tt0   = t_grp * 2;
    const int oo0   = o_grp * 8;

    // ---- stage x2 tile transposed: X2s[j][t] ----
    for (int q = tid; q < TB * (IN2 / 4); q += THREADS) {   // 1024 float4
        int t  = q >> 4;        // token in tile (0..63)
        int j4 = q & 15;        // j quad
        float4 v = *(const float4*)&x2[(size_t)(tok0 + t) * IN2 + j4 * 4];
        X2s[j4 * 4 + 0][t] = v.x;
        X2s[j4 * 4 + 1][t] = v.y;
        X2s[j4 * 4 + 2][t] = v.z;
        X2s[j4 * 4 + 3][t] = v.w;
    }

    // ---- prologue: prefetch W chunk 0 (registers) + x1 column 0 ----
    const float4* wt4 = (const float4*)g_Wt;
    float4 p[4];
#pragma unroll
    for (int u = 0; u < 4; ++u) p[u] = wt4[u * THREADS + tid];
    float x1v[2];
#pragma unroll
    for (int tt = 0; tt < 2; ++tt)
        x1v[tt] = x1[(size_t)(tok0 + tt0 + tt) * IN1 + 0];

    unsigned long long acc[2][4];
#pragma unroll
    for (int tt = 0; tt < 2; ++tt)
#pragma unroll
        for (int q = 0; q < 4; ++q) acc[tt][q] = 0ULL;   // = {0.f, 0.f}

    for (int c = 0; c < NCHUNK; ++c) {
        __syncthreads();                       // previous chunk compute done
#pragma unroll
        for (int u = 0; u < 4; ++u) Wbuf4[u * THREADS + tid] = p[u];
        __syncthreads();                       // Wbuf ready

        // prefetch chunk c+1 while computing chunk c (latency hidden by compute)
        const int cn = c + 1;
        float x1n[2] = {1.0f, 1.0f};
        if (cn < NCHUNK) {
#pragma unroll
            for (int u = 0; u < 4; ++u)
                p[u] = wt4[(size_t)cn * 1024 + u * THREADS + tid];
            if (cn < IN1) {
#pragma unroll
                for (int tt = 0; tt < 2; ++tt)
                    x1n[tt] = x1[(size_t)(tok0 + tt0 + tt) * IN1 + cn];
            }
        }

        const float* wb = (const float*)Wbuf4;
#pragma unroll 8
        for (int j = 0; j < IN2; ++j) {
            // x2 for this thread's 2 tokens
            float2 x2v = *(const float2*)&X2s[j][tt0];
            // B fragment: 8 outputs = 4 f32x2 pairs (16B-aligned since oo0 % 8 == 0)
            const ulonglong2* brow = (const ulonglong2*)&wb[j * OUTDIM + oo0];
            ulonglong2 b01 = brow[0];
            ulonglong2 b23 = brow[1];

            float a0 = x1v[0] * x2v.x;
            float a1 = x1v[1] * x2v.y;
            unsigned long long ad0, ad1;
            asm("mov.b64 %0, {%1, %1};" : "=l"(ad0) : "f"(a0));
            asm("mov.b64 %0, {%1, %1};" : "=l"(ad1) : "f"(a1));

            asm("fma.rn.f32x2 %0, %1, %2, %0;" : "+l"(acc[0][0]) : "l"(ad0), "l"(b01.x));
            asm("fma.rn.f32x2 %0, %1, %2, %0;" : "+l"(acc[0][1]) : "l"(ad0), "l"(b01.y));
            asm("fma.rn.f32x2 %0, %1, %2, %0;" : "+l"(acc[0][2]) : "l"(ad0), "l"(b23.x));
            asm("fma.rn.f32x2 %0, %1, %2, %0;" : "+l"(acc[0][3]) : "l"(ad0), "l"(b23.y));
            asm("fma.rn.f32x2 %0, %1, %2, %0;" : "+l"(acc[1][0]) : "l"(ad1), "l"(b01.x));
            asm("fma.rn.f32x2 %0, %1, %2, %0;" : "+l"(acc[1][1]) : "l"(ad1), "l"(b01.y));
            asm("fma.rn.f32x2 %0, %1, %2, %0;" : "+l"(acc[1][2]) : "l"(ad1), "l"(b23.x));
            asm("fma.rn.f32x2 %0, %1, %2, %0;" : "+l"(acc[1][3]) : "l"(ad1), "l"(b23.y));
        }
#pragma unroll
        for (int tt = 0; tt < 2; ++tt) x1v[tt] = x1n[tt];
    }

    // ---- epilogue: each thread writes 2 tokens x 8 outputs ----
#pragma unroll
    for (int tt = 0; tt < 2; ++tt) {
        size_t base = (size_t)(tok0 + tt0 + tt) * OUTDIM + oo0;  // 32B aligned
        ulonglong2* dst = (ulonglong2*)&out[base];
        dst[0] = make_ulonglong2(acc[tt][0], acc[tt][1]);
        dst[1] = make_ulonglong2(acc[tt][2], acc[tt][3]);
    }
}

// ---------------------------------------------------------------------------
extern "C" void kernel_launch(void* const* d_in, const int* in_sizes, int n_in,
                              void* d_out, int out_size) {
    const float* x1   = (const float*)d_in[0];   // (4,4096,256)
    const float* x2   = (const float*)d_in[1];   // (4,4096,64)
    const float* W    = (const float*)d_in[2];   // (4096,256)
    const float* bvec = (const float*)d_in[3];   // (4096,)
    float*       out  = (float*)d_out;           // (4,4096,64)

    const int T = in_sizes[0] / IN1;             // 16384 tokens

    prep_transpose<<<dim3(IN1 / 32, (IN2 * OUTDIM) / 32), dim3(32, 8)>>>(W);
    prep_bias<<<(IN2 * OUTDIM) / 256, 256>>>(bvec);
    metalinear_kernel<<<T / TB, THREADS>>>(x1, x2, out);
}

// round 11
// speedup vs baseline: 1.1431x; 1.1431x over previous
#include <cuda_runtime.h>

// metaLinear: y[t,o] = sum_{i,j} x1[t,i]*x2[t,j]*W[j*64+o, i] + sum_j x2[t,j]*b[j*64+o]
// GEMM form with x1 factored per-chunk:
//   chunk c (= i), v[t][o] = sum_j x2[t,j] * Wt[c*64+j][o] ;  y[t][o] += x1[t,c] * v[t][o]
//   chunk 256 = bias rows with x1 == 1.

#define IN1     256
#define IN2     64
#define OUTDIM  64
#define KTOT    (IN1 * IN2)      // 16384
#define NCHUNK  (IN1 + 1)        // 257 (last = bias)
#define TB      64               // tokens per CTA
#define THREADS 128

__device__ float g_Wt[(KTOT + IN2) * OUTDIM];   // 4.21 MB scratch (L2-resident)

#define FMA2(acc, a, b) \
    asm("fma.rn.f32x2 %0, %1, %2, %0;" : "+l"(acc) : "l"(a), "l"(b))

// ---------------------------------------------------------------------------
// Prep 1: tiled transpose  W(4096 x 256) -> Wt[i*64+j][o]  (r = j*64+o)
// ---------------------------------------------------------------------------
__global__ void prep_transpose(const float* __restrict__ W) {
    __shared__ float tile[32][33];
    const int ib = blockIdx.x * 32;
    const int rb = blockIdx.y * 32;
    const int tx = threadIdx.x;
    const int ty = threadIdx.y;
#pragma unroll
    for (int yy = 0; yy < 32; yy += 8)
        tile[ty + yy][tx] = W[(size_t)(rb + ty + yy) * IN1 + (ib + tx)];
    __syncthreads();
#pragma unroll
    for (int yy = 0; yy < 32; yy += 8)
        g_Wt[(size_t)(ib + ty + yy) * (IN2 * OUTDIM) + (rb + tx)] = tile[tx][ty + yy];
}

__global__ void prep_bias(const float* __restrict__ bvec) {
    int m = blockIdx.x * 256 + threadIdx.x;
    g_Wt[(size_t)KTOT * OUTDIM + m] = bvec[m];
}

// ---------------------------------------------------------------------------
// Main GEMM. 128 threads / CTA, 64 tokens x 64 outputs per CTA.
// Thread micro-tile: 4 tokens x 8 outputs (as 4 f32x2 output-pairs).
//   t_grp = tid>>3 (0..15) -> t0 = 4*t_grp ; o_grp = tid&7 -> o0 = 8*o_grp
// W chunk (64 j x 64 o = 16 KB) double-buffered in smem via cp.async.
// ---------------------------------------------------------------------------
__global__ __launch_bounds__(THREADS) void metalinear_kernel(
    const float* __restrict__ x1,
    const float* __restrict__ x2,
    float* __restrict__ out)
{
    __shared__ __align__(16) float X2s[IN2][TB];          // [j][t]  16 KB
    __shared__ __align__(16) float Ws[2][IN2][OUTDIM];    // 32 KB double buffer

    const int tid  = threadIdx.x;
    const int tok0 = blockIdx.x * TB;
    const int t0   = (tid >> 3) * 4;
    const int o0   = (tid & 7) * 8;

    // ---- stage x2 tile transposed: X2s[j][t] ----
    for (int q = tid; q < TB * (IN2 / 4); q += THREADS) {   // 1024 float4
        int t  = q >> 4;
        int j4 = q & 15;
        float4 vv = *(const float4*)&x2[(size_t)(tok0 + t) * IN2 + j4 * 4];
        X2s[j4 * 4 + 0][t] = vv.x;
        X2s[j4 * 4 + 1][t] = vv.y;
        X2s[j4 * 4 + 2][t] = vv.z;
        X2s[j4 * 4 + 3][t] = vv.w;
    }

    // ---- async-copy chunk 0 into Ws[0] ----
    {
        unsigned dst = (unsigned)__cvta_generic_to_shared(&Ws[0][0][0]);
        const float* src = g_Wt;
#pragma unroll
        for (int u = 0; u < 8; ++u) {
            int q = u * THREADS + tid;            // float4 index 0..1023
            asm volatile("cp.async.cg.shared.global [%0], [%1], 16;"
                         :: "r"(dst + q * 16), "l"(src + q * 4));
        }
        asm volatile("cp.async.commit_group;");
    }

    float x1v[4], x1n[4] = {1.f, 1.f, 1.f, 1.f};
#pragma unroll
    for (int tt = 0; tt < 4; ++tt)
        x1v[tt] = x1[(size_t)(tok0 + t0 + tt) * IN1];

    unsigned long long y[4][4], v[4][4];
#pragma unroll
    for (int t = 0; t < 4; ++t)
#pragma unroll
        for (int m = 0; m < 4; ++m) { y[t][m] = 0ULL; v[t][m] = 0ULL; }

    for (int c = 0; c < NCHUNK; ++c) {
        if (c > 0) __syncthreads();               // buffer (c+1)&1 now free
        const int cn = c + 1;
        if (cn < NCHUNK) {
            // issue next chunk's copies while chunk c's (issued last iter) land
            unsigned dst = (unsigned)__cvta_generic_to_shared(&Ws[cn & 1][0][0]);
            const float* src = g_Wt + (size_t)cn * 64 * OUTDIM;
#pragma unroll
            for (int u = 0; u < 8; ++u) {
                int q = u * THREADS + tid;
                asm volatile("cp.async.cg.shared.global [%0], [%1], 16;"
                             :: "r"(dst + q * 16), "l"(src + q * 4));
            }
            asm volatile("cp.async.commit_group;");
#pragma unroll
            for (int tt = 0; tt < 4; ++tt)
                x1n[tt] = (cn < IN1) ? x1[(size_t)(tok0 + t0 + tt) * IN1 + cn]
                                     : 1.0f;
            asm volatile("cp.async.wait_group 1;");   // chunk c complete
        } else {
            asm volatile("cp.async.wait_group 0;");
        }
        __syncthreads();                          // chunk c visible to all

        const float* wsb = &Ws[c & 1][0][0];
#pragma unroll 8
        for (int j = 0; j < IN2; ++j) {
            // A: this thread's 4 tokens of x2 (1 LDS.128, conflict-free)
            float4 a = *(const float4*)&X2s[j][t0];
            unsigned long long ad0, ad1, ad2, ad3;
            asm("mov.b64 %0, {%1, %1};" : "=l"(ad0) : "f"(a.x));
            asm("mov.b64 %0, {%1, %1};" : "=l"(ad1) : "f"(a.y));
            asm("mov.b64 %0, {%1, %1};" : "=l"(ad2) : "f"(a.z));
            asm("mov.b64 %0, {%1, %1};" : "=l"(ad3) : "f"(a.w));
            // B: 8 outputs = 4 f32x2 pairs (2 LDS.128)
            const ulonglong2* bp = (const ulonglong2*)(wsb + j * OUTDIM + o0);
            ulonglong2 b01 = bp[0];
            ulonglong2 b23 = bp[1];

            FMA2(v[0][0], ad0, b01.x); FMA2(v[0][1], ad0, b01.y);
            FMA2(v[0][2], ad0, b23.x); FMA2(v[0][3], ad0, b23.y);
            FMA2(v[1][0], ad1, b01.x); FMA2(v[1][1], ad1, b01.y);
            FMA2(v[1][2], ad1, b23.x); FMA2(v[1][3], ad1, b23.y);
            FMA2(v[2][0], ad2, b01.x); FMA2(v[2][1], ad2, b01.y);
            FMA2(v[2][2], ad2, b23.x); FMA2(v[2][3], ad2, b23.y);
            FMA2(v[3][0], ad3, b01.x); FMA2(v[3][1], ad3, b01.y);
            FMA2(v[3][2], ad3, b23.x); FMA2(v[3][3], ad3, b23.y);
        }

        // ---- per-chunk epilogue: y += x1[.,c] * v ; v = 0 ----
        unsigned long long xd[4];
#pragma unroll
        for (int tt = 0; tt < 4; ++tt)
            asm("mov.b64 %0, {%1, %1};" : "=l"(xd[tt]) : "f"(x1v[tt]));
#pragma unroll
        for (int t = 0; t < 4; ++t)
#pragma unroll
            for (int m = 0; m < 4; ++m) {
                FMA2(y[t][m], xd[t], v[t][m]);
                v[t][m] = 0ULL;
            }
#pragma unroll
        for (int tt = 0; tt < 4; ++tt) x1v[tt] = x1n[tt];
    }

    // ---- final store: 4 tokens x 8 contiguous outputs each ----
#pragma unroll
    for (int t = 0; t < 4; ++t) {
        ulonglong2* dst = (ulonglong2*)&out[(size_t)(tok0 + t0 + t) * OUTDIM + o0];
        dst[0] = make_ulonglong2(y[t][0], y[t][1]);
        dst[1] = make_ulonglong2(y[t][2], y[t][3]);
    }
}

// ---------------------------------------------------------------------------
extern "C" void kernel_launch(void* const* d_in, const int* in_sizes, int n_in,
                              void* d_out, int out_size) {
    const float* x1   = (const float*)d_in[0];   // (4,4096,256)
    const float* x2   = (const float*)d_in[1];   // (4,4096,64)
    const float* W    = (const float*)d_in[2];   // (4096,256)
    const float* bvec = (const float*)d_in[3];   // (4096,)
    float*       out  = (float*)d_out;           // (4,4096,64)

    const int T = in_sizes[0] / IN1;             // 16384 tokens

    prep_transpose<<<dim3(IN1 / 32, (IN2 * OUTDIM) / 32), dim3(32, 8)>>>(W);
    prep_bias<<<(IN2 * OUTDIM) / 256, 256>>>(bvec);
    metalinear_kernel<<<T / TB, THREADS>>>(x1, x2, out);
}

// round 13
// speedup vs baseline: 7.6229x; 6.6687x over previous
#include <cuda_runtime.h>
#include <cuda_bf16.h>
#include <cstdint>

// metaLinear via warp-level bf16x3 mma.sync (arch-portable, no tcgen05):
//   chunk c (=i, 0..255): V[t][o] = sum_j x2[t,j]*W[(j*64+o),c] ; y += x1[t,c]*V
//   chunk 256: bias rows, scale 1.
// fp32 ~= Ah*Bh + Ah*Bl + Al*Bh  (bf16 hi/lo split; lo*lo dropped, ~2^-18)
// mma m16n8k16: m=tokens, k=j(64), n=o(64). A (x2 splits) register-resident
// across ALL chunks; B (W splits) streamed in prebaked fragment order.

#define IN1     256
#define IN2     64
#define OUTDIM  64
#define NCHUNK  257
#define TTOT    16384
#define TB      64          // tokens per CTA
#define THREADS 128

// B fragments, frag-ordered per chunk: [c][kt(4)][s(2)][nw(2)][lane(32)][r(8)] u32
// r = ntl*2 + q ; value = pack(bf16 B[k][n], bf16 B[k+1][n]), k = kt*16+t4*2+q*8,
// n = nw*32 + ntl*8 + g   (g = lane>>2, t4 = lane&3). 16KB per chunk.
__device__ __align__(16) uint32_t g_Wf[NCHUNK * 4096];          // 4.2 MB
__device__ float g_x1T[IN1 * TTOT];                             // 16.8 MB

__device__ __forceinline__ uint32_t pack_hi(float a, float b) {
    __nv_bfloat162 t{__float2bfloat16(a), __float2bfloat16(b)};
    return *reinterpret_cast<uint32_t*>(&t);
}
__device__ __forceinline__ float bf_res(float a) {              // a - bf16(a)
    return a - __bfloat162float(__float2bfloat16(a));
}
__device__ __forceinline__ uint32_t pack_lo(float a, float b) {
    __nv_bfloat162 t{__float2bfloat16(bf_res(a)), __float2bfloat16(bf_res(b))};
    return *reinterpret_cast<uint32_t*>(&t);
}

// D = A*B + D   (m16n8k16 row.col f32.bf16)
__device__ __forceinline__ void mma_acc(float* d, const uint32_t* a,
                                        uint32_t b0, uint32_t b1) {
    asm volatile("mma.sync.aligned.m16n8k16.row.col.f32.bf16.bf16.f32 "
        "{%0,%1,%2,%3}, {%4,%5,%6,%7}, {%8,%9}, {%0,%1,%2,%3};"
        : "+f"(d[0]), "+f"(d[1]), "+f"(d[2]), "+f"(d[3])
        : "r"(a[0]), "r"(a[1]), "r"(a[2]), "r"(a[3]), "r"(b0), "r"(b1));
}
// D = A*B  (zero C)
__device__ __forceinline__ void mma_zero(float* d, const uint32_t* a,
                                         uint32_t b0, uint32_t b1) {
    asm volatile("mma.sync.aligned.m16n8k16.row.col.f32.bf16.bf16.f32 "
        "{%0,%1,%2,%3}, {%4,%5,%6,%7}, {%8,%9}, {%10,%10,%10,%10};"
        : "=f"(d[0]), "=f"(d[1]), "=f"(d[2]), "=f"(d[3])
        : "r"(a[0]), "r"(a[1]), "r"(a[2]), "r"(a[3]), "r"(b0), "r"(b1),
          "f"(0.0f));
}

// ---------------------------------------------------------------------------
// Prep 1: bake W (+bias) into per-chunk B fragments (hi/lo splits).
// idx < 256*4096: c = idx&255 (coalesced W reads), pos = idx>>8.
// ---------------------------------------------------------------------------
__global__ void prep_wfrag(const float* __restrict__ W,
                           const float* __restrict__ bvec) {
    int idx = blockIdx.x * 256 + threadIdx.x;
    if (idx >= NCHUNK * 4096) return;
    int c, pos;
    if (idx < 256 * 4096) { c = idx & 255; pos = idx >> 8; }
    else                  { c = 256; pos = idx - 256 * 4096; }

    int r    = pos & 7;
    int lane = (pos >> 3) & 31;
    int nw   = (pos >> 8) & 1;
    int s    = (pos >> 9) & 1;
    int kt   = pos >> 10;
    int g = lane >> 2, t4 = lane & 3;
    int q = r & 1, ntl = r >> 1;
    int n  = nw * 32 + ntl * 8 + g;          // o
    int k0 = kt * 16 + t4 * 2 + q * 8;       // j

    float w0, w1;
    if (c < 256) {
        w0 = W[(size_t)(k0 * 64 + n) * IN1 + c];
        w1 = W[(size_t)((k0 + 1) * 64 + n) * IN1 + c];
    } else {
        w0 = bvec[k0 * 64 + n];
        w1 = bvec[(k0 + 1) * 64 + n];
    }
    g_Wf[(size_t)c * 4096 + pos] = s ? pack_lo(w0, w1) : pack_hi(w0, w1);
}

// Prep 2: tiled transpose x1(16384 x 256) -> g_x1T[i][t]
__global__ void prep_x1T(const float* __restrict__ x1) {
    __shared__ float tile[32][33];
    const int tb = blockIdx.x * 32, ib = blockIdx.y * 32;
    const int tx = threadIdx.x, ty = threadIdx.y;
#pragma unroll
    for (int yy = 0; yy < 32; yy += 8)
        tile[ty + yy][tx] = x1[(size_t)(tb + ty + yy) * IN1 + ib + tx];
    __syncthreads();
#pragma unroll
    for (int yy = 0; yy < 32; yy += 8)
        g_x1T[(size_t)(ib + ty + yy) * TTOT + tb + tx] = tile[tx][ty + yy];
}

// ---------------------------------------------------------------------------
// Main: 256 CTAs x 128 thr. CTA tile 64 tok x 64 out; warp grid 2(m) x 2(n),
// warp tile 32x32. A (x2 hi/lo) resident in regs; B streamed via 3-stage
// cp.async ring of frag-ordered chunks.
// ---------------------------------------------------------------------------
__global__ __launch_bounds__(THREADS) void metalinear_mma(
    const float* __restrict__ x2, float* __restrict__ out)
{
    __shared__ __align__(16) uint32_t Bs[3][4096];   // 48 KB

    const int tid  = threadIdx.x;
    const int warp = tid >> 5, lane = tid & 31;
    const int g = lane >> 2, t4 = lane & 3;
    const int mw = warp >> 1, nw = warp & 1;
    const int tok0 = blockIdx.x * TB;
    const int m0 = mw * 32;
    const int fbase = (nw * 32 + lane) * 8;

    // ---- resident A fragments: x2 hi/lo, 2 m-tiles x 4 k-tiles ----
    uint32_t ah[2][4][4], al[2][4][4];
#pragma unroll
    for (int mt = 0; mt < 2; ++mt)
#pragma unroll
        for (int kt = 0; kt < 4; ++kt) {
            int ta = tok0 + m0 + mt * 16 + g;
            int j0 = kt * 16 + t4 * 2;
            float2 xa0 = *(const float2*)&x2[(size_t)ta * IN2 + j0];
            float2 xa2 = *(const float2*)&x2[(size_t)ta * IN2 + j0 + 8];
            float2 xb0 = *(const float2*)&x2[(size_t)(ta + 8) * IN2 + j0];
            float2 xb2 = *(const float2*)&x2[(size_t)(ta + 8) * IN2 + j0 + 8];
            ah[mt][kt][0] = pack_hi(xa0.x, xa0.y);
            ah[mt][kt][1] = pack_hi(xb0.x, xb0.y);
            ah[mt][kt][2] = pack_hi(xa2.x, xa2.y);
            ah[mt][kt][3] = pack_hi(xb2.x, xb2.y);
            al[mt][kt][0] = pack_lo(xa0.x, xa0.y);
            al[mt][kt][1] = pack_lo(xb0.x, xb0.y);
            al[mt][kt][2] = pack_lo(xa2.x, xa2.y);
            al[mt][kt][3] = pack_lo(xb2.x, xb2.y);
        }

    // ---- cp.async helpers (8 x 16B per thread per chunk) ----
    auto cp_chunk = [&](int buf, int c) {
        uint32_t dst = (uint32_t)__cvta_generic_to_shared(&Bs[buf][0]);
        const char* src = (const char*)(g_Wf + (size_t)c * 4096);
#pragma unroll
        for (int u = 0; u < 8; ++u) {
            int q = u * THREADS + tid;
            asm volatile("cp.async.cg.shared.global [%0], [%1], 16;"
                         :: "r"(dst + q * 16), "l"(src + q * 16));
        }
        asm volatile("cp.async.commit_group;");
    };

    cp_chunk(0, 0);
    cp_chunk(1, 1);

    float y[2][4][4];
#pragma unroll
    for (int mt = 0; mt < 2; ++mt)
#pragma unroll
        for (int nt = 0; nt < 4; ++nt)
#pragma unroll
            for (int e = 0; e < 4; ++e) y[mt][nt][e] = 0.f;

    for (int c = 0; c < NCHUNK; ++c) {
        __syncthreads();                       // all warps done with chunk c-1
        if (c + 2 < NCHUNK) cp_chunk((c + 2) % 3, c + 2);
        if (c < NCHUNK - 2)
            asm volatile("cp.async.wait_group 2;" ::: "memory");
        else if (c == NCHUNK - 2)
            asm volatile("cp.async.wait_group 1;" ::: "memory");
        else
            asm volatile("cp.async.wait_group 0;" ::: "memory");
        __syncthreads();                       // chunk c visible to all warps

        const uint32_t* F = &Bs[c % 3][0];
        float v[2][4][4];

#pragma unroll
        for (int kt = 0; kt < 4; ++kt) {
            const uint4* hp = (const uint4*)&F[kt * 1024 + fbase];
            const uint4* lp = (const uint4*)&F[kt * 1024 + 512 + fbase];
            uint4 h0 = hp[0], h1 = hp[1];
            uint4 l0 = lp[0], l1 = lp[1];
#pragma unroll
            for (int mt = 0; mt < 2; ++mt) {
                const uint32_t* AH = ah[mt][kt];
                const uint32_t* AL = al[mt][kt];
                if (kt == 0) {
                    mma_zero(v[mt][0], AH, h0.x, h0.y);
                    mma_zero(v[mt][1], AH, h0.z, h0.w);
                    mma_zero(v[mt][2], AH, h1.x, h1.y);
                    mma_zero(v[mt][3], AH, h1.z, h1.w);
                } else {
                    mma_acc(v[mt][0], AH, h0.x, h0.y);
                    mma_acc(v[mt][1], AH, h0.z, h0.w);
                    mma_acc(v[mt][2], AH, h1.x, h1.y);
                    mma_acc(v[mt][3], AH, h1.z, h1.w);
                }
                mma_acc(v[mt][0], AH, l0.x, l0.y);   // Ah*Bl
                mma_acc(v[mt][1], AH, l0.z, l0.w);
                mma_acc(v[mt][2], AH, l1.x, l1.y);
                mma_acc(v[mt][3], AH, l1.z, l1.w);
                mma_acc(v[mt][0], AL, h0.x, h0.y);   // Al*Bh
                mma_acc(v[mt][1], AL, h0.z, h0.w);
                mma_acc(v[mt][2], AL, h1.x, h1.y);
                mma_acc(v[mt][3], AL, h1.z, h1.w);
            }
        }

        // ---- per-chunk scale-accumulate: y += x1[t,c] * v ----
        float s0 = 1.f, s1 = 1.f, s2 = 1.f, s3 = 1.f;
        if (c < 256) {
            const float* xr = &g_x1T[(size_t)c * TTOT + tok0 + m0 + g];
            s0 = __ldg(xr);      s1 = __ldg(xr + 8);
            s2 = __ldg(xr + 16); s3 = __ldg(xr + 24);
        }
#pragma unroll
        for (int nt = 0; nt < 4; ++nt) {
            y[0][nt][0] = fmaf(s0, v[0][nt][0], y[0][nt][0]);
            y[0][nt][1] = fmaf(s0, v[0][nt][1], y[0][nt][1]);
            y[0][nt][2] = fmaf(s1, v[0][nt][2], y[0][nt][2]);
            y[0][nt][3] = fmaf(s1, v[0][nt][3], y[0][nt][3]);
            y[1][nt][0] = fmaf(s2, v[1][nt][0], y[1][nt][0]);
            y[1][nt][1] = fmaf(s2, v[1][nt][1], y[1][nt][1]);
            y[1][nt][2] = fmaf(s3, v[1][nt][2], y[1][nt][2]);
            y[1][nt][3] = fmaf(s3, v[1][nt][3], y[1][nt][3]);
        }
    }

    // ---- store: D frag rows g / g+8 per m-tile, cols t4*2 within n-tiles ----
#pragma unroll
    for (int mt = 0; mt < 2; ++mt) {
        int r0 = tok0 + m0 + mt * 16 + g;
#pragma unroll
        for (int nt = 0; nt < 4; ++nt) {
            int col = nw * 32 + nt * 8 + t4 * 2;
            *(float2*)&out[(size_t)r0 * OUTDIM + col] =
                make_float2(y[mt][nt][0], y[mt][nt][1]);
            *(float2*)&out[(size_t)(r0 + 8) * OUTDIM + col] =
                make_float2(y[mt][nt][2], y[mt][nt][3]);
        }
    }
}

// ---------------------------------------------------------------------------
extern "C" void kernel_launch(void* const* d_in, const int* in_sizes, int n_in,
                              void* d_out, int out_size) {
    const float* x1   = (const float*)d_in[0];   // (4,4096,256)
    const float* x2   = (const float*)d_in[1];   // (4,4096,64)
    const float* W    = (const float*)d_in[2];   // (4096,256)
    const float* bvec = (const float*)d_in[3];   // (4096,)
    float*       out  = (float*)d_out;           // (4,4096,64)

    prep_wfrag<<<(NCHUNK * 4096 + 255) / 256, 256>>>(W, bvec);
    prep_x1T<<<dim3(TTOT / 32, IN1 / 32), dim3(32, 8)>>>(x1);
    metalinear_mma<<<TTOT / TB, THREADS>>>(x2, out);
}

// round 15
// speedup vs baseline: 7.8991x; 1.0362x over previous
#include <cuda_runtime.h>
#include <cuda_bf16.h>
#include <cstdint>

// metaLinear via warp-level bf16x3 mma.sync:
//   chunk c (=i, 0..255): V[t][o] = sum_j x2[t,j]*W[(j*64+o),c] ; y += x1[t,c]*V
//   chunk 256: bias rows, scale 1.
// fp32 ~= Ah*Bh + Ah*Bl + Al*Bh  (bf16 hi/lo split; lo*lo dropped)
// mma m16n8k16: m=tokens, k=j(64), n=o(64). A (x2 splits) register-resident
// across ALL chunks; B (W splits) streamed in prebaked fragment order.
// R14: TB=128 / 256 thr (1 CTA/SM, half the B L2 traffic, no stragglers),
//      x1 scales prefetched before the mma block (hide L2 latency).

#define IN1     256
#define IN2     64
#define OUTDIM  64
#define NCHUNK  257
#define TTOT    16384
#define TB      128         // tokens per CTA
#define THREADS 256

// B fragments, frag-ordered per chunk: [c][kt(4)][s(2)][nw(2)][lane(32)][r(8)] u32
// r = ntl*2 + q ; value = pack(bf16 B[k][n], bf16 B[k+1][n]), k = kt*16+t4*2+q*8,
// n = nw*32 + ntl*8 + g   (g = lane>>2, t4 = lane&3). 16KB per chunk.
__device__ __align__(16) uint32_t g_Wf[NCHUNK * 4096];          // 4.2 MB
__device__ float g_x1T[IN1 * TTOT];                             // 16.8 MB

__device__ __forceinline__ uint32_t pack_hi(float a, float b) {
    __nv_bfloat162 t{__float2bfloat16(a), __float2bfloat16(b)};
    return *reinterpret_cast<uint32_t*>(&t);
}
__device__ __forceinline__ float bf_res(float a) {              // a - bf16(a)
    return a - __bfloat162float(__float2bfloat16(a));
}
__device__ __forceinline__ uint32_t pack_lo(float a, float b) {
    __nv_bfloat162 t{__float2bfloat16(bf_res(a)), __float2bfloat16(bf_res(b))};
    return *reinterpret_cast<uint32_t*>(&t);
}

// D = A*B + D   (m16n8k16 row.col f32.bf16)
__device__ __forceinline__ void mma_acc(float* d, const uint32_t* a,
                                        uint32_t b0, uint32_t b1) {
    asm volatile("mma.sync.aligned.m16n8k16.row.col.f32.bf16.bf16.f32 "
        "{%0,%1,%2,%3}, {%4,%5,%6,%7}, {%8,%9}, {%0,%1,%2,%3};"
        : "+f"(d[0]), "+f"(d[1]), "+f"(d[2]), "+f"(d[3])
        : "r"(a[0]), "r"(a[1]), "r"(a[2]), "r"(a[3]), "r"(b0), "r"(b1));
}
// D = A*B  (zero C)
__device__ __forceinline__ void mma_zero(float* d, const uint32_t* a,
                                         uint32_t b0, uint32_t b1) {
    asm volatile("mma.sync.aligned.m16n8k16.row.col.f32.bf16.bf16.f32 "
        "{%0,%1,%2,%3}, {%4,%5,%6,%7}, {%8,%9}, {%10,%10,%10,%10};"
        : "=f"(d[0]), "=f"(d[1]), "=f"(d[2]), "=f"(d[3])
        : "r"(a[0]), "r"(a[1]), "r"(a[2]), "r"(a[3]), "r"(b0), "r"(b1),
          "f"(0.0f));
}

// ---------------------------------------------------------------------------
// Prep 1: bake W (+bias) into per-chunk B fragments (hi/lo splits).
// ---------------------------------------------------------------------------
__global__ void prep_wfrag(const float* __restrict__ W,
                           const float* __restrict__ bvec) {
    int idx = blockIdx.x * 256 + threadIdx.x;
    if (idx >= NCHUNK * 4096) return;
    int c, pos;
    if (idx < 256 * 4096) { c = idx & 255; pos = idx >> 8; }
    else                  { c = 256; pos = idx - 256 * 4096; }

    int r    = pos & 7;
    int lane = (pos >> 3) & 31;
    int nw   = (pos >> 8) & 1;
    int s    = (pos >> 9) & 1;
    int kt   = pos >> 10;
    int g = lane >> 2, t4 = lane & 3;
    int q = r & 1, ntl = r >> 1;
    int n  = nw * 32 + ntl * 8 + g;          // o
    int k0 = kt * 16 + t4 * 2 + q * 8;       // j

    float w0, w1;
    if (c < 256) {
        w0 = W[(size_t)(k0 * 64 + n) * IN1 + c];
        w1 = W[(size_t)((k0 + 1) * 64 + n) * IN1 + c];
    } else {
        w0 = bvec[k0 * 64 + n];
        w1 = bvec[(k0 + 1) * 64 + n];
    }
    g_Wf[(size_t)c * 4096 + pos] = s ? pack_lo(w0, w1) : pack_hi(w0, w1);
}

// Prep 2: tiled transpose x1(16384 x 256) -> g_x1T[i][t]
__global__ void prep_x1T(const float* __restrict__ x1) {
    __shared__ float tile[32][33];
    const int tb = blockIdx.x * 32, ib = blockIdx.y * 32;
    const int tx = threadIdx.x, ty = threadIdx.y;
#pragma unroll
    for (int yy = 0; yy < 32; yy += 8)
        tile[ty + yy][tx] = x1[(size_t)(tb + ty + yy) * IN1 + ib + tx];
    __syncthreads();
#pragma unroll
    for (int yy = 0; yy < 32; yy += 8)
        g_x1T[(size_t)(ib + ty + yy) * TTOT + tb + tx] = tile[tx][ty + yy];
}

// ---------------------------------------------------------------------------
// Main: 128 CTAs x 256 thr (1 CTA/SM). CTA tile 128 tok x 64 out; warp grid
// 4(m) x 2(n), warp tile 32x32. A resident in regs; B via 3-stage cp.async.
// ---------------------------------------------------------------------------
__global__ __launch_bounds__(THREADS, 1) void metalinear_mma(
    const float* __restrict__ x2, float* __restrict__ out)
{
    __shared__ __align__(16) uint32_t Bs[3][4096];   // 48 KB

    const int tid  = threadIdx.x;
    const int warp = tid >> 5, lane = tid & 31;
    const int g = lane >> 2, t4 = lane & 3;
    const int mw = warp >> 1, nw = warp & 1;
    const int tok0 = blockIdx.x * TB;
    const int m0 = mw * 32;
    const int fbase = (nw * 32 + lane) * 8;

    // ---- resident A fragments: x2 hi/lo, 2 m-tiles x 4 k-tiles ----
    uint32_t ah[2][4][4], al[2][4][4];
#pragma unroll
    for (int mt = 0; mt < 2; ++mt)
#pragma unroll
        for (int kt = 0; kt < 4; ++kt) {
            int ta = tok0 + m0 + mt * 16 + g;
            int j0 = kt * 16 + t4 * 2;
            float2 xa0 = *(const float2*)&x2[(size_t)ta * IN2 + j0];
            float2 xa2 = *(const float2*)&x2[(size_t)ta * IN2 + j0 + 8];
            float2 xb0 = *(const float2*)&x2[(size_t)(ta + 8) * IN2 + j0];
            float2 xb2 = *(const float2*)&x2[(size_t)(ta + 8) * IN2 + j0 + 8];
            ah[mt][kt][0] = pack_hi(xa0.x, xa0.y);
            ah[mt][kt][1] = pack_hi(xb0.x, xb0.y);
            ah[mt][kt][2] = pack_hi(xa2.x, xa2.y);
            ah[mt][kt][3] = pack_hi(xb2.x, xb2.y);
            al[mt][kt][0] = pack_lo(xa0.x, xa0.y);
            al[mt][kt][1] = pack_lo(xb0.x, xb0.y);
            al[mt][kt][2] = pack_lo(xa2.x, xa2.y);
            al[mt][kt][3] = pack_lo(xb2.x, xb2.y);
        }

    // ---- cp.async: 16 KB per chunk, 4 x 16B per thread ----
    auto cp_chunk = [&](int buf, int c) {
        uint32_t dst = (uint32_t)__cvta_generic_to_shared(&Bs[buf][0]);
        const char* src = (const char*)(g_Wf + (size_t)c * 4096);
#pragma unroll
        for (int u = 0; u < 4; ++u) {
            int q = u * THREADS + tid;
            asm volatile("cp.async.cg.shared.global [%0], [%1], 16;"
                         :: "r"(dst + q * 16), "l"(src + q * 16));
        }
        asm volatile("cp.async.commit_group;");
    };

    cp_chunk(0, 0);
    cp_chunk(1, 1);

    float y[2][4][4];
#pragma unroll
    for (int mt = 0; mt < 2; ++mt)
#pragma unroll
        for (int nt = 0; nt < 4; ++nt)
#pragma unroll
            for (int e = 0; e < 4; ++e) y[mt][nt][e] = 0.f;

    for (int c = 0; c < NCHUNK; ++c) {
        __syncthreads();                       // all warps done with chunk c-1
        if (c + 2 < NCHUNK) cp_chunk((c + 2) % 3, c + 2);
        if (c < NCHUNK - 2)
            asm volatile("cp.async.wait_group 2;" ::: "memory");
        else if (c == NCHUNK - 2)
            asm volatile("cp.async.wait_group 1;" ::: "memory");
        else
            asm volatile("cp.async.wait_group 0;" ::: "memory");
        __syncthreads();                       // chunk c visible to all warps

        // ---- prefetch x1 scales EARLY: latency hidden behind the mma block
        float s0 = 1.f, s1 = 1.f, s2 = 1.f, s3 = 1.f;
        if (c < 256) {
            const float* xr = &g_x1T[(size_t)c * TTOT + tok0 + m0 + g];
            s0 = __ldg(xr);      s1 = __ldg(xr + 8);
            s2 = __ldg(xr + 16); s3 = __ldg(xr + 24);
        }

        const uint32_t* F = &Bs[c % 3][0];
        float v[2][4][4];

#pragma unroll
        for (int kt = 0; kt < 4; ++kt) {
            const uint4* hp = (const uint4*)&F[kt * 1024 + fbase];
            const uint4* lp = (const uint4*)&F[kt * 1024 + 512 + fbase];
            uint4 h0 = hp[0], h1 = hp[1];
            uint4 l0 = lp[0], l1 = lp[1];
#pragma unroll
            for (int mt = 0; mt < 2; ++mt) {
                const uint32_t* AH = ah[mt][kt];
                const uint32_t* AL = al[mt][kt];
                if (kt == 0) {
                    mma_zero(v[mt][0], AH, h0.x, h0.y);
                    mma_zero(v[mt][1], AH, h0.z, h0.w);
                    mma_zero(v[mt][2], AH, h1.x, h1.y);
                    mma_zero(v[mt][3], AH, h1.z, h1.w);
                } else {
                    mma_acc(v[mt][0], AH, h0.x, h0.y);
                    mma_acc(v[mt][1], AH, h0.z, h0.w);
                    mma_acc(v[mt][2], AH, h1.x, h1.y);
                    mma_acc(v[mt][3], AH, h1.z, h1.w);
                }
                mma_acc(v[mt][0], AH, l0.x, l0.y);   // Ah*Bl
                mma_acc(v[mt][1], AH, l0.z, l0.w);
                mma_acc(v[mt][2], AH, l1.x, l1.y);
                mma_acc(v[mt][3], AH, l1.z, l1.w);
                mma_acc(v[mt][0], AL, h0.x, h0.y);   // Al*Bh
                mma_acc(v[mt][1], AL, h0.z, h0.w);
                mma_acc(v[mt][2], AL, h1.x, h1.y);
                mma_acc(v[mt][3], AL, h1.z, h1.w);
            }
        }

        // ---- per-chunk scale-accumulate: y += x1[t,c] * v ----
#pragma unroll
        for (int nt = 0; nt < 4; ++nt) {
            y[0][nt][0] = fmaf(s0, v[0][nt][0], y[0][nt][0]);
            y[0][nt][1] = fmaf(s0, v[0][nt][1], y[0][nt][1]);
            y[0][nt][2] = fmaf(s1, v[0][nt][2], y[0][nt][2]);
            y[0][nt][3] = fmaf(s1, v[0][nt][3], y[0][nt][3]);
            y[1][nt][0] = fmaf(s2, v[1][nt][0], y[1][nt][0]);
            y[1][nt][1] = fmaf(s2, v[1][nt][1], y[1][nt][1]);
            y[1][nt][2] = fmaf(s3, v[1][nt][2], y[1][nt][2]);
            y[1][nt][3] = fmaf(s3, v[1][nt][3], y[1][nt][3]);
        }
    }

    // ---- store ----
#pragma unroll
    for (int mt = 0; mt < 2; ++mt) {
        int r0 = tok0 + m0 + mt * 16 + g;
#pragma unroll
        for (int nt = 0; nt < 4; ++nt) {
            int col = nw * 32 + nt * 8 + t4 * 2;
            *(float2*)&out[(size_t)r0 * OUTDIM + col] =
                make_float2(y[mt][nt][0], y[mt][nt][1]);
            *(float2*)&out[(size_t)(r0 + 8) * OUTDIM + col] =
                make_float2(y[mt][nt][2], y[mt][nt][3]);
        }
    }
}

// ---------------------------------------------------------------------------
extern "C" void kernel_launch(void* const* d_in, const int* in_sizes, int n_in,
                              void* d_out, int out_size) {
    const float* x1   = (const float*)d_in[0];   // (4,4096,256)
    const float* x2   = (const float*)d_in[1];   // (4,4096,64)
    const float* W    = (const float*)d_in[2];   // (4096,256)
    const float* bvec = (const float*)d_in[3];   // (4096,)
    float*       out  = (float*)d_out;           // (4,4096,64)

    prep_wfrag<<<(NCHUNK * 4096 + 255) / 256, 256>>>(W, bvec);
    prep_x1T<<<dim3(TTOT / 32, IN1 / 32), dim3(32, 8)>>>(x1);
    metalinear_mma<<<TTOT / TB, THREADS>>>(x2, out);
}